// round 5
// baseline (speedup 1.0000x reference)
#include <cuda_runtime.h>
#include <cstdint>

#define NQ    65536
#define BQ    256
#define HIDQ  64
#define TPB   256
#define TILE  1024
#define RROWS 8
#define SCAP  520   // 19 sigma above mean c3=256; inline fallback guards the rest

__device__ __forceinline__ float tanhax(float x) {
    float y; asm("tanh.approx.f32 %0, %1;" : "=f"(y) : "f"(x)); return y;
}

__global__ __launch_bounds__(TPB) void soen_kernel(
    const float* __restrict__ phi, const float* __restrict__ s,
    const float* __restrict__ i_b, const float* __restrict__ w1,
    const float* __restrict__ b1,  const float* __restrict__ w2,
    const float* __restrict__ b2,  const int* __restrict__ fidx,
    float* __restrict__ out)
{
    __shared__ float4 q4[HIDQ];            // (w1[0][k], w1[1][k], w1[2][k], b1[k])
    __shared__ float  vv[HIDQ];            // w2[k]
    __shared__ int    cnt3;
    __shared__ int    col3[SCAP];
    __shared__ float  st_p[RROWS][SCAP];   // func3 stash: periodic(phi)
    __shared__ float  st_s[RROWS][SCAP];   // func3 stash: s

    const int t        = threadIdx.x;
    const int lane     = t & 31;
    const int tileBase = blockIdx.x * TILE;
    const int r0       = blockIdx.y * RROWS;

    if (t < HIDQ) {
        q4[t] = make_float4(w1[t], w1[HIDQ + t], w1[2 * HIDQ + t], b1[t]);
        vv[t] = w2[t];
    }
    if (t == 0) cnt3 = 0;
    __syncthreads();

    // ---- compaction: func3 columns of this tile (thread t owns cols 4t..4t+3) ----
    const int4 fi4 = ((const int4*)(fidx + tileBase))[t];
    int f[4] = {fi4.x, fi4.y, fi4.z, fi4.w};
    int myrank[4];
#pragma unroll
    for (int e = 0; e < 4; e++) {
        const unsigned mask = __ballot_sync(0xffffffffu, f[e] == 3);
        int rank = -1;
        if (mask) {
            const int leader = __ffs(mask) - 1;
            int base = 0;
            if (lane == leader) base = atomicAdd(&cnt3, __popc(mask));
            base = __shfl_sync(0xffffffffu, base, leader);
            if (f[e] == 3) {
                rank = base + __popc(mask & ((1u << lane) - 1u));
                if (rank < SCAP) col3[rank] = 4 * t + e;
            }
        }
        myrank[e] = rank;
    }
    __syncthreads();
    const int   c3    = cnt3;
    const float bias2 = b2[0];

    // ---- Phase A: stream; cheap funcs direct-stored; func3 (p,s) stashed to SMEM ----
#pragma unroll
    for (int rr = 0; rr < RROWS; rr++) {
        const size_t rowOff = (size_t)(r0 + rr) * NQ + tileBase;
        const float4 ph4 = ((const float4*)(phi + rowOff))[t];
        const float4 sv4 = ((const float4*)(s   + rowOff))[t];
        const float phv[4] = {ph4.x, ph4.y, ph4.z, ph4.w};
        const float svv[4] = {sv4.x, sv4.y, sv4.z, sv4.w};
#pragma unroll
        for (int e = 0; e < 4; e++) {
            const float p  = phv[e] - rintf(phv[e]);
            const float sv = svv[e];
            if (f[e] == 3) {
                const int rk = myrank[e];
                if (rk < SCAP) {
                    st_p[rr][rk] = p; st_s[rr][rk] = sv;
                } else {
                    // never-taken overflow fallback: inline MLP for this element
                    const float ibv = __ldg(i_b + tileBase + 4 * t + e);
                    float acc = bias2;
                    for (int k = 0; k < HIDQ; k++) {
                        const float4 w = q4[k];
                        const float  z = fmaf(p, w.x, fmaf(sv, w.y, fmaf(ibv, w.z, w.w)));
                        acc = fmaf(tanhax(z), vv[k], acc);
                    }
                    out[rowOff + 4 * t + e] = acc;
                }
            } else {
                const float g0 = fmaxf(fabsf(p) - sv, 0.0f);
                const float g1 = tanhax(p) * (1.0f - sv);
                const float g2 = exp2f(p * p * (-14.4269504088896340736f)) - sv;
                out[rowOff + 4 * t + e] = (f[e] == 0) ? g0 : ((f[e] == 1) ? g1 : g2);
            }
        }
    }
    __syncthreads();

    // ---- Phase B: items = (func3 column) x (4-row half) ----
    const int ccap  = (c3 < SCAP) ? c3 : SCAP;
    const int items = 2 * ccap;
    for (int j = t; j < items; j += TPB) {
        const int col   = (j < ccap) ? j : (j - ccap);
        const int rbase = (j < ccap) ? 0 : 4;
        const int lc    = col3[col];
        const float ibv = __ldg(i_b + tileBase + lc);

        float p[4], sv[4], acc[4];
#pragma unroll
        for (int i = 0; i < 4; i++) {
            p[i]   = st_p[rbase + i][col];
            sv[i]  = st_s[rbase + i][col];
            acc[i] = bias2;
        }

#pragma unroll 8
        for (int k = 0; k < HIDQ; k++) {
            const float4 w  = q4[k];
            const float  ck = fmaf(ibv, w.z, w.w);
            const float  v  = vv[k];
#pragma unroll
            for (int i = 0; i < 4; i++) {
                const float z = fmaf(p[i], w.x, fmaf(sv[i], w.y, ck));
                acc[i] = fmaf(tanhax(z), v, acc[i]);
            }
        }

        const size_t base = (size_t)(r0 + rbase) * NQ + tileBase + lc;
#pragma unroll
        for (int i = 0; i < 4; i++)
            out[base + (size_t)i * NQ] = acc[i];
    }
}

extern "C" void kernel_launch(void* const* d_in, const int* in_sizes, int n_in,
                              void* d_out, int out_size)
{
    const float* phi  = (const float*)d_in[0];
    const float* s    = (const float*)d_in[1];
    const float* i_b  = (const float*)d_in[2];
    const float* w1   = (const float*)d_in[3];
    const float* b1   = (const float*)d_in[4];
    const float* w2   = (const float*)d_in[5];
    const float* b2   = (const float*)d_in[6];
    const int*   fidx = (const int*)d_in[7];
    float*       out  = (float*)d_out;

    // Max shared carveout so 4 blocks (36.6KB each) fit per SM -> 32 resident warps
    cudaFuncSetAttribute(soen_kernel, cudaFuncAttributePreferredSharedMemoryCarveout, 100);

    dim3 grid(NQ / TILE, BQ / RROWS);   // (64, 32) = 2048 blocks
    soen_kernel<<<grid, TPB>>>(phi, s, i_b, w1, b1, w2, b2, fidx, out);
}